// round 4
// baseline (speedup 1.0000x reference)
#include <cuda_runtime.h>

#define NN 50000
#define BB 8
#define BN (BB*NN)
#define DD 64
#define HISTLEN 50
#define LE_CAP (1<<22)

// ---------------- static device scratch (no runtime allocation) ----------------
__device__ float g_cl, g_cr, g_el0, g_er0;
__device__ float g_wal[DD], g_war[DD], g_h0[DD], g_H0[DD], g_G1[DD], g_G0[DD];

__device__ unsigned g_code[NN];
__device__ int      g_deg[NN];
__device__ unsigned g_mask[NN];
__device__ unsigned g_counts[BN];
__device__ int      g_mcount[BN];
__device__ float    g_dphir[BN];
__device__ int      g_idxK[BN];
__device__ int      g_idx2[BN];
__device__ float    g_sk_s[BN];
__device__ int      g_sk_i[BN];
__device__ float    g_philc[BN];
__device__ float    g_basew[BN];
__device__ float    g_denom[BN];
__device__ int      g_bslot[BN];
__device__ float    g_H2c[(size_t)BN*DD];
__device__ float    g_numer[(size_t)BN*DD];
__device__ int      g_le_k[LE_CAP];
__device__ int      g_le_i[LE_CAP];
__device__ int g_ctrK, g_ctr2, g_ctrE, g_deg0, g_touch[BB];

// grid barrier state (count always returns to 0; gen monotonically increases across replays)
__device__ unsigned g_bar_count;
__device__ volatile unsigned g_bar_gen;

__device__ __forceinline__ float leakyf(float x){ return x > 0.f ? x : 0.2f*x; }

__device__ __forceinline__ void gridsync(){
    __syncthreads();
    if (threadIdx.x == 0){
        __threadfence();
        unsigned gen = g_bar_gen;
        unsigned my = atomicAdd(&g_bar_count, 1u);
        if (my == gridDim.x - 1u){
            atomicExch(&g_bar_count, 0u);
            __threadfence();
            g_bar_gen = gen + 1u;
        } else {
            while (g_bar_gen == gen) { }
        }
        __threadfence();
    }
    __syncthreads();
}

__device__ __forceinline__ void scan1_edge(int sv, int dv){
    atomicAdd(&g_deg[dv], 1);
    unsigned c = __ldg((const unsigned*)&g_code[sv]);
    if (c){
        do {
            int bit = __ffs(c) - 1;
            int b   = bit >> 2;
            unsigned cls = (c >> (4*b)) & 0xFu;
            c &= ~(0xFu << (4*b));
            atomicAdd(&g_counts[b*NN + dv], 1u << (10*(cls-1)));
        } while (c);
    }
}

__device__ __forceinline__ void scan2_edge(int sv, int dv){
    unsigned m = g_mask[sv];
    if (!m) return;
    do {
        int b = __ffs(m) - 1; m &= m - 1;
        int i2 = b*NN + dv;
        atomicAdd(&g_mcount[i2], 1);
        int p = atomicAdd(&g_ctrE, 1);
        if (p < LE_CAP){
            g_le_k[p] = g_idxK[b*NN + sv];
            g_le_i[p] = i2;
        }
    } while (m);
}

__global__ void __launch_bounds__(256, 2) fused(
    const int* __restrict__ hist, const int* __restrict__ exits, int n_exits,
    const int* __restrict__ src, const int* __restrict__ dst, int E,
    const float* __restrict__ W1, const float* __restrict__ al1,
    const float* __restrict__ ar1, const float* __restrict__ b1,
    const float* __restrict__ W2, const float* __restrict__ al2,
    const float* __restrict__ ar2, const float* __restrict__ b2,
    float* out)
{
    __shared__ float sW2[DD*DD];
    __shared__ float sh1[8][DD];
    __shared__ float sacc[BB][DD];
    __shared__ float scst[4*DD];   // W1 | b1 | wal | war

    const int tid  = threadIdx.x;
    const int bid  = blockIdx.x;
    const int G    = gridDim.x;
    const int gsz  = G*256;
    const int gtid = bid*256 + tid;

    // ---------- P0: zero everything ----------
    for (int i = gtid; i < BN; i += gsz){ g_counts[i] = 0u; g_mcount[i] = 0; g_dphir[i] = 0.f; }
    for (int i = gtid; i < NN; i += gsz){ g_code[i] = 0u; g_deg[i] = 0; g_mask[i] = 0u; }
    if (gtid < BB*DD) out[gtid] = 0.f;
    if (gtid < BB)    g_touch[gtid] = 0;
    if (gtid == 0){ g_ctrK = 0; g_ctr2 = 0; g_ctrE = 0; g_deg0 = 0; }
    gridsync();

    // ---------- P1: block0 = feature scatter; block1 = weight constants ----------
    if (bid == 0){
        // exits (1) < visited (2) < current (3); later phases win
        for (int i = tid; i < BB*n_exits; i += 256){
            int b = i / n_exits; int v = exits[i - b*n_exits];
            atomicOr(&g_code[v], 1u << (4*b));
        }
        __syncthreads();
        for (int i = tid; i < BB*(HISTLEN-1); i += 256){
            int b = i / (HISTLEN-1); int j = i - b*(HISTLEN-1);
            int v = hist[b*HISTLEN + j]; int sh = 4*b;
            atomicAnd(&g_code[v], ~(0xFu << sh));
            atomicOr (&g_code[v], 2u << sh);
        }
        __syncthreads();
        if (tid < BB){
            int v = hist[tid*HISTLEN + HISTLEN-1]; int sh = 4*tid;
            atomicAnd(&g_code[v], ~(0xFu << sh));
            atomicOr (&g_code[v], 3u << sh);
        }
    } else if (bid == 1){
        if (tid < DD){
            float wl = 0.f, wr = 0.f;
            for (int j = 0; j < DD; j++){ float w = W2[tid*DD + j]; wl += w*al2[j]; wr += w*ar2[j]; }
            g_wal[tid] = wl; g_war[tid] = wr;
            g_h0[tid] = fmaxf(b1[tid], 0.f);
        }
        __syncthreads();
        if (tid < DD){
            float h = 0.f;
            for (int j = 0; j < DD; j++) h += g_h0[j]*W2[j*DD + tid];
            g_H0[tid] = h;
            g_G1[tid] = fmaxf(h + b2[tid], 0.f);
            g_G0[tid] = fmaxf(b2[tid], 0.f);
        }
        if (tid == 0){
            float cl = 0.f, cr = 0.f;
            for (int j = 0; j < DD; j++){ cl += W1[j]*al1[j]; cr += W1[j]*ar1[j]; }
            g_cl = cl; g_cr = cr;
        }
        __syncthreads();
        if (tid == 0){
            float el = 0.f, er = 0.f;
            for (int j = 0; j < DD; j++){ el += g_h0[j]*g_wal[j]; er += g_h0[j]*g_war[j]; }
            g_el0 = el; g_er0 = er;
        }
    }
    gridsync();

    // ---------- P2: edge scan 1 (degrees + class counts), vectorized ----------
    {
        int E4 = E >> 2;
        const int4* s4 = (const int4*)src;
        const int4* d4 = (const int4*)dst;
        for (int i = gtid; i < E4; i += gsz){
            int4 sv = __ldg(&s4[i]); int4 dv = __ldg(&d4[i]);
            scan1_edge(sv.x, dv.x); scan1_edge(sv.y, dv.y);
            scan1_edge(sv.z, dv.z); scan1_edge(sv.w, dv.w);
        }
        for (int i = (E4 << 2) + gtid; i < E; i += gsz) scan1_edge(src[i], dst[i]);
    }
    gridsync();

    // ---------- P3: per-(b,v) scalar s + compaction ----------
    {
        float cl = g_cl, cr = g_cr;
        for (int i = gtid; i < BN; i += gsz){
            int b = i / NN, v = i - b*NN;
            unsigned c = g_counts[i];
            if (b == 0 && g_deg[v] == 0) atomicAdd(&g_deg0, 1);
            if (c == 0) continue;
            int degv = g_deg[v];
            int n1 = c & 1023, n2 = (c >> 10) & 1023, n3 = (c >> 20) & 1023;
            int n0 = degv - n1 - n2 - n3;
            unsigned clsv = (g_code[v] >> (4*b)) & 0xFu;
            float fd = (clsv == 0) ? 0.f : (clsv == 1 ? 1.0f : (clsv == 2 ? 0.1f : 0.5f));
            float crfd = cr*fd;
            float w0 = (n0 > 0) ? n0*expf(leakyf(crfd))           : 0.f;
            float w1 = (n1 > 0) ? n1*expf(leakyf(cl*1.0f + crfd)) : 0.f;
            float w2 = (n2 > 0) ? n2*expf(leakyf(cl*0.1f + crfd)) : 0.f;
            float w3 = (n3 > 0) ? n3*expf(leakyf(cl*0.5f + crfd)) : 0.f;
            float s = (1.0f*w1 + 0.1f*w2 + 0.5f*w3) / (w0 + w1 + w2 + w3);
            int k = atomicAdd(&g_ctrK, 1);
            g_sk_s[k] = s; g_sk_i[k] = i; g_idxK[i] = k;
            atomicOr(&g_mask[v], 1u << b);
        }
    }
    gridsync();

    // ---------- P4: per special slot: phi_l, dphir, H2(s)  (warp per slot) ----------
    {
        for (int j = tid; j < DD*DD; j += 256) sW2[j] = W2[j];
        if (tid < DD){
            scst[tid]        = W1[tid];
            scst[DD + tid]   = b1[tid];
            scst[2*DD + tid] = g_wal[tid];
            scst[3*DD + tid] = g_war[tid];
        }
        __syncthreads();
        int K = g_ctrK;
        int wid = tid >> 5, lane = tid & 31;
        int gwarp = bid*8 + wid, nwarp = G*8;
        float er0 = g_er0;
        for (int k = gwarp; k < K; k += nwarp){
            float s = g_sk_s[k];
            float h0 = fmaxf(s*scst[lane]      + scst[DD + lane],      0.f);
            float h1 = fmaxf(s*scst[lane + 32] + scst[DD + lane + 32], 0.f);
            sh1[wid][lane] = h0; sh1[wid][lane + 32] = h1;
            float pl = h0*scst[2*DD + lane] + h1*scst[2*DD + lane + 32];
            float pr = h0*scst[3*DD + lane] + h1*scst[3*DD + lane + 32];
            #pragma unroll
            for (int o = 16; o; o >>= 1){
                pl += __shfl_xor_sync(0xffffffffu, pl, o);
                pr += __shfl_xor_sync(0xffffffffu, pr, o);
            }
            __syncwarp();
            if (lane == 0){
                g_philc[k] = pl;
                g_dphir[g_sk_i[k]] = pr - er0;
            }
            float a0 = 0.f, a1 = 0.f;
            #pragma unroll 8
            for (int j = 0; j < DD; j++){
                float hv = sh1[wid][j];
                a0 += hv*sW2[j*DD + lane];
                a1 += hv*sW2[j*DD + lane + 32];
            }
            g_H2c[(size_t)k*DD + lane]      = a0;
            g_H2c[(size_t)k*DD + lane + 32] = a1;
            __syncwarp();
        }
    }
    gridsync();

    // ---------- P5: edge scan 2 (special-edge compaction), vectorized ----------
    {
        int E4 = E >> 2;
        const int4* s4 = (const int4*)src;
        const int4* d4 = (const int4*)dst;
        for (int i = gtid; i < E4; i += gsz){
            int4 sv = __ldg(&s4[i]); int4 dv = __ldg(&d4[i]);
            scan2_edge(sv.x, dv.x); scan2_edge(sv.y, dv.y);
            scan2_edge(sv.z, dv.z); scan2_edge(sv.w, dv.w);
        }
        for (int i = (E4 << 2) + gtid; i < E; i += gsz) scan2_edge(src[i], dst[i]);
    }
    gridsync();

    // ---------- P6: touched-dst slot compaction + base mass ----------
    {
        float el0 = g_el0, er0 = g_er0;
        for (int i = gtid; i < BN; i += gsz){
            int mc = g_mcount[i];
            if (!mc) continue;
            int b = i / NN, v = i - b*NN;
            int nb = g_deg[v] - mc;
            float bw = 0.f;
            if (nb > 0) bw = (float)nb * expf(leakyf(el0 + er0 + g_dphir[i]));
            int slot = atomicAdd(&g_ctr2, 1);
            g_idx2[i] = slot; g_basew[slot] = bw;
            g_denom[slot] = bw; g_bslot[slot] = b;
            float4 z = make_float4(0.f, 0.f, 0.f, 0.f);
            float4* p = (float4*)&g_numer[(size_t)slot*DD];
            #pragma unroll
            for (int j = 0; j < DD/4; j++) p[j] = z;
            atomicAdd(&g_touch[b], 1);
        }
    }
    gridsync();

    // ---------- P7: accumulate special messages (warp per compact edge) ----------
    {
        int wid = tid >> 5, lane = tid & 31;
        int gwarp = bid*8 + wid, nwarp = G*8;
        int Etot = g_ctrE; if (Etot > LE_CAP) Etot = LE_CAP;
        float er0 = g_er0;
        for (int e = gwarp; e < Etot; e += nwarp){
            int k  = g_le_k[e];
            int i2 = g_le_i[e];
            float lg = leakyf(g_philc[k] + er0 + g_dphir[i2]);
            float w  = expf(lg);
            int slot = g_idx2[i2];
            if (lane == 0) atomicAdd(&g_denom[slot], w);
            const float* h2 = &g_H2c[(size_t)k*DD];
            float* nu = &g_numer[(size_t)slot*DD];
            atomicAdd(&nu[lane],      w*h2[lane]);
            atomicAdd(&nu[lane + 32], w*h2[lane + 32]);
        }
    }
    gridsync();

    // ---------- P8: finalize: relu + batch mean ----------
    {
        for (int j = tid; j < BB*DD; j += 256) ((float*)sacc)[j] = 0.f;
        __syncthreads();
        int S = g_ctr2;
        int grp = tid >> 6, lt = tid & 63;
        float H0t = g_H0[lt], b2t = b2[lt];
        for (int slot = bid*4 + grp; slot < S; slot += G*4){
            int b = g_bslot[slot];
            float den = g_denom[slot], bw = g_basew[slot];
            float val = (g_numer[(size_t)slot*DD + lt] + bw*H0t) / den + b2t;
            val = fmaxf(val, 0.f);
            if (val != 0.f) atomicAdd(&sacc[b][lt], val);
        }
        __syncthreads();
        const float inv = 1.0f / (float)NN;
        if (tid < DD){
            #pragma unroll
            for (int b = 0; b < BB; b++){
                float a = sacc[b][tid];
                if (bid == 0){
                    float gp = (float)(NN - g_deg0 - g_touch[b]);
                    a += gp*g_G1[tid] + (float)g_deg0*g_G0[tid];
                }
                if (a != 0.f) atomicAdd(&out[b*DD + tid], a*inv);
            }
        }
    }
}

// ---------------- launch ----------------
extern "C" void kernel_launch(void* const* d_in, const int* in_sizes, int n_in,
                              void* d_out, int out_size){
    const int*   hist  = (const int*)  d_in[0];
    const int*   exits = (const int*)  d_in[1];
    const int*   src   = (const int*)  d_in[2];
    const int*   dst   = (const int*)  d_in[3];
    const float* W1    = (const float*)d_in[4];
    const float* al1   = (const float*)d_in[5];
    const float* ar1   = (const float*)d_in[6];
    const float* b1    = (const float*)d_in[7];
    const float* W2    = (const float*)d_in[8];
    const float* al2   = (const float*)d_in[9];
    const float* ar2   = (const float*)d_in[10];
    const float* b2    = (const float*)d_in[11];
    float* out = (float*)d_out;
    int E   = in_sizes[2];
    int nex = in_sizes[1];

    int dev = 0, sms = 148;
    cudaGetDevice(&dev);
    cudaDeviceGetAttribute(&sms, cudaDevAttrMultiProcessorCount, dev);
    // __launch_bounds__(256, 2) guarantees >= 2 resident blocks/SM -> all co-resident
    int G = 2*sms;
    if (G < 2) G = 2;

    fused<<<G, 256>>>(hist, exits, nex, src, dst, E,
                      W1, al1, ar1, b1, W2, al2, ar2, b2, out);
}

// round 6
// speedup vs baseline: 1.1263x; 1.1263x over previous
#include <cuda_runtime.h>

#define NN 50000
#define BB 8
#define BN (BB*NN)
#define DD 64
#define HISTLEN 50
#define K_CAP (1<<17)
#define CH_CAP (1<<22)

// ---------------- static device scratch (no runtime allocation) ----------------
__device__ float g_cl, g_cr, g_el0, g_er0;
__device__ float g_wal[DD], g_war[DD], g_h0[DD], g_H0[DD], g_G1[DD], g_G0[DD];

__device__ unsigned g_code[NN];      // 4-bit feature class per batch, packed
__device__ int      g_deg[NN];       // in-degree
__device__ unsigned g_mask[NN];      // per-node bitmask of batches with s!=0
__device__ unsigned g_counts[BN];    // packed n1|n2|n3 (10 bits each), layer-1
__device__ float    g_dphir[BN];     // phi_r(s) - er0 (0 for s==0)
__device__ int      g_idxK[BN];      // (b,v) -> special-source slot k
__device__ int      g_head[BN];      // chain head per (b,dst), -1 = untouched
__device__ float    g_sk_s[K_CAP];   // s per special slot
__device__ int      g_sk_i[K_CAP];   // (b,v) index per special slot
__device__ float    g_philc[K_CAP];  // phi_l per special slot
__device__ float    g_H2c[(size_t)K_CAP*DD]; // H2(s) per special slot
__device__ int      g_ch_k[CH_CAP];  // chain node: special-source slot
__device__ int      g_ch_nx[CH_CAP]; // chain node: next pointer
__device__ int g_ctrK, g_ctrC, g_deg0;

__device__ __forceinline__ float leakyf(float x){ return x > 0.f ? x : 0.2f*x; }

// ---------------- K_A: init + feature scatter + weight constants ----------------
__global__ void k_init(const int* __restrict__ hist, const int* __restrict__ exits, int n_exits,
                       const float* __restrict__ W1, const float* __restrict__ al1,
                       const float* __restrict__ ar1, const float* __restrict__ b1,
                       const float* __restrict__ W2, const float* __restrict__ al2,
                       const float* __restrict__ ar2, const float* __restrict__ b2,
                       float* out){
    int tid = threadIdx.x, bid = blockIdx.x;
    if (bid == 0){
        // zero g_code, then scatter feature classes (block-local ordering)
        for (int i = tid; i < NN; i += 256) g_code[i] = 0u;
        __syncthreads();
        for (int i = tid; i < BB*n_exits; i += 256){
            int b = i / n_exits; int v = exits[i - b*n_exits];
            atomicOr(&g_code[v], 1u << (4*b));
        }
        __syncthreads();
        for (int i = tid; i < BB*(HISTLEN-1); i += 256){
            int b = i / (HISTLEN-1); int j = i - b*(HISTLEN-1);
            int v = hist[b*HISTLEN + j]; int sh = 4*b;
            atomicAnd(&g_code[v], ~(0xFu << sh));
            atomicOr (&g_code[v], 2u << sh);
        }
        __syncthreads();
        if (tid < BB){
            int v = hist[tid*HISTLEN + HISTLEN-1]; int sh = 4*tid;
            atomicAnd(&g_code[v], ~(0xFu << sh));
            atomicOr (&g_code[v], 3u << sh);
        }
    } else if (bid == 1){
        if (tid < DD){
            float wl = 0.f, wr = 0.f;
            for (int j = 0; j < DD; j++){ float w = W2[tid*DD + j]; wl += w*al2[j]; wr += w*ar2[j]; }
            g_wal[tid] = wl; g_war[tid] = wr;
            g_h0[tid] = fmaxf(b1[tid], 0.f);
        }
        __syncthreads();
        if (tid < DD){
            float h = 0.f;
            for (int j = 0; j < DD; j++) h += g_h0[j]*W2[j*DD + tid];
            g_H0[tid] = h;
            g_G1[tid] = fmaxf(h + b2[tid], 0.f);
            g_G0[tid] = fmaxf(b2[tid], 0.f);
        }
        if (tid == 0){
            float cl = 0.f, cr = 0.f;
            for (int j = 0; j < DD; j++){ cl += W1[j]*al1[j]; cr += W1[j]*ar1[j]; }
            g_cl = cl; g_cr = cr;
        }
        __syncthreads();
        if (tid == 0){
            float el = 0.f, er = 0.f;
            for (int j = 0; j < DD; j++){ el += g_h0[j]*g_wal[j]; er += g_h0[j]*g_war[j]; }
            g_el0 = el; g_er0 = er;
        }
        if (tid == 32){ g_ctrK = 0; g_ctrC = 0; g_deg0 = 0; }
    } else {
        // blocks >= 2: zero the big dense arrays
        int g = (bid - 2)*256 + tid;
        int gs = (gridDim.x - 2)*256;
        for (int i = g; i < BN; i += gs){
            g_counts[i] = 0u; g_dphir[i] = 0.f; g_head[i] = -1;
        }
        for (int i = g; i < NN; i += gs){ g_deg[i] = 0; g_mask[i] = 0u; }
        if (g < BB*DD) out[g] = 0.f;
    }
}

// ---------------- K_B: full edge scan -> degrees + layer-1 class counts ----------------
__device__ __forceinline__ void scan1_edge(int sv, int dv){
    atomicAdd(&g_deg[dv], 1);
    unsigned c = __ldg(&g_code[sv]);
    if (c){
        do {
            int bit = __ffs(c) - 1;
            int b   = bit >> 2;
            unsigned cls = (c >> (4*b)) & 0xFu;
            c &= ~(0xFu << (4*b));
            atomicAdd(&g_counts[b*NN + dv], 1u << (10*(cls-1)));
        } while (c);
    }
}

__global__ void k_scan1(const int* __restrict__ src, const int* __restrict__ dst, int E){
    int g = blockIdx.x*blockDim.x + threadIdx.x;
    int gs = gridDim.x*blockDim.x;
    int E4 = E >> 2;
    const int4* s4 = (const int4*)src;
    const int4* d4 = (const int4*)dst;
    for (int i = g; i < E4; i += gs){
        int4 sv = __ldg(&s4[i]); int4 dv = __ldg(&d4[i]);
        scan1_edge(sv.x, dv.x); scan1_edge(sv.y, dv.y);
        scan1_edge(sv.z, dv.z); scan1_edge(sv.w, dv.w);
    }
    for (int i = (E4 << 2) + g; i < E; i += gs) scan1_edge(src[i], dst[i]);
}

// ---------------- K_C: per-(b,v) scalar s + special compaction + deg0 ----------------
__global__ void k_node(){
    int g = blockIdx.x*blockDim.x + threadIdx.x;
    int gs = gridDim.x*blockDim.x;
    float cl = g_cl, cr = g_cr;
    for (int i = g; i < BN; i += gs){
        int b = i / NN, v = i - b*NN;
        unsigned c = g_counts[i];
        if (b == 0 && g_deg[v] == 0) atomicAdd(&g_deg0, 1);
        if (c == 0) continue;
        int degv = g_deg[v];
        int n1 = c & 1023, n2 = (c >> 10) & 1023, n3 = (c >> 20) & 1023;
        int n0 = degv - n1 - n2 - n3;
        unsigned clsv = (g_code[v] >> (4*b)) & 0xFu;
        float fd = (clsv == 0) ? 0.f : (clsv == 1 ? 1.0f : (clsv == 2 ? 0.1f : 0.5f));
        float crfd = cr*fd;
        float w0 = (n0 > 0) ? n0*expf(leakyf(crfd))           : 0.f;
        float w1 = (n1 > 0) ? n1*expf(leakyf(cl*1.0f + crfd)) : 0.f;
        float w2 = (n2 > 0) ? n2*expf(leakyf(cl*0.1f + crfd)) : 0.f;
        float w3 = (n3 > 0) ? n3*expf(leakyf(cl*0.5f + crfd)) : 0.f;
        float s = (1.0f*w1 + 0.1f*w2 + 0.5f*w3) / (w0 + w1 + w2 + w3);
        int k = atomicAdd(&g_ctrK, 1);
        if (k < K_CAP){
            g_sk_s[k] = s; g_sk_i[k] = i; g_idxK[i] = k;
            atomicOr(&g_mask[v], 1u << b);
        }
    }
}

// ---------------- K_DE: slotcalc (warp/slot) + edge scan 2 (chain push) ----------------
__device__ __forceinline__ void scan2_edge(int sv, int dv){
    unsigned m = g_mask[sv];
    if (!m) return;
    do {
        int b = __ffs(m) - 1; m &= m - 1;
        int i2 = b*NN + dv;
        int pos = atomicAdd(&g_ctrC, 1);
        if (pos < CH_CAP){
            g_ch_k[pos] = g_idxK[b*NN + sv];
            int old = atomicExch(&g_head[i2], pos);
            g_ch_nx[pos] = old;
        }
    } while (m);
}

__global__ void k_de(const float* __restrict__ W1, const float* __restrict__ b1,
                     const float* __restrict__ W2,
                     const int* __restrict__ src, const int* __restrict__ dst, int E){
    __shared__ float sW2[DD*DD];
    __shared__ float sh1[8][DD];
    __shared__ float scst[4*DD];   // W1 | b1 | wal | war
    int tid = threadIdx.x;
    for (int j = tid; j < DD*DD; j += 256) sW2[j] = W2[j];
    if (tid < DD){
        scst[tid]        = W1[tid];
        scst[DD + tid]   = b1[tid];
        scst[2*DD + tid] = g_wal[tid];
        scst[3*DD + tid] = g_war[tid];
    }
    __syncthreads();

    // phase 1: per-slot phil / dphir / H2 (warp per slot)
    {
        int K = g_ctrK; if (K > K_CAP) K = K_CAP;
        int wid = tid >> 5, lane = tid & 31;
        int gwarp = blockIdx.x*8 + wid, nwarp = gridDim.x*8;
        float er0 = g_er0;
        for (int k = gwarp; k < K; k += nwarp){
            float s = g_sk_s[k];
            float h0 = fmaxf(s*scst[lane]      + scst[DD + lane],      0.f);
            float h1 = fmaxf(s*scst[lane + 32] + scst[DD + lane + 32], 0.f);
            sh1[wid][lane] = h0; sh1[wid][lane + 32] = h1;
            float pl = h0*scst[2*DD + lane] + h1*scst[2*DD + lane + 32];
            float pr = h0*scst[3*DD + lane] + h1*scst[3*DD + lane + 32];
            #pragma unroll
            for (int o = 16; o; o >>= 1){
                pl += __shfl_xor_sync(0xffffffffu, pl, o);
                pr += __shfl_xor_sync(0xffffffffu, pr, o);
            }
            __syncwarp();
            if (lane == 0){
                g_philc[k] = pl;
                g_dphir[g_sk_i[k]] = pr - er0;
            }
            float a0 = 0.f, a1 = 0.f;
            #pragma unroll 8
            for (int j = 0; j < DD; j++){
                float hv = sh1[wid][j];
                a0 += hv*sW2[j*DD + lane];
                a1 += hv*sW2[j*DD + lane + 32];
            }
            g_H2c[(size_t)k*DD + lane]      = a0;
            g_H2c[(size_t)k*DD + lane + 32] = a1;
            __syncwarp();
        }
    }

    // phase 2: edge scan (no dependence on phase 1 outputs)
    {
        int g = blockIdx.x*blockDim.x + tid;
        int gs = gridDim.x*blockDim.x;
        int E4 = E >> 2;
        const int4* s4 = (const int4*)src;
        const int4* d4 = (const int4*)dst;
        for (int i = g; i < E4; i += gs){
            int4 sv = __ldg(&s4[i]); int4 dv = __ldg(&d4[i]);
            scan2_edge(sv.x, dv.x); scan2_edge(sv.y, dv.y);
            scan2_edge(sv.z, dv.z); scan2_edge(sv.w, dv.w);
        }
        for (int i = (E4 << 2) + g; i < E; i += gs) scan2_edge(src[i], dst[i]);
    }
}

// ---------------- K_F: chain walk + finalize ----------------
// out = (1/N)[ (N-deg0)*G1 + deg0*G0 + sum_touched (relu(val) - G1) ]
__global__ void k_final(float* out, const float* __restrict__ b2){
    int tid = threadIdx.x;
    int lane = tid & 31;
    int gwarp = (blockIdx.x*blockDim.x + tid) >> 5;
    int nwarp = (gridDim.x*blockDim.x) >> 5;
    const float inv = 1.0f / (float)NN;

    // constant part (block 0 only, once)
    if (blockIdx.x == 0){
        int d0 = g_deg0;
        for (int j = tid; j < BB*DD; j += blockDim.x){
            int d = j & (DD-1);
            float cst = (float)(NN - d0)*g_G1[d] + (float)d0*g_G0[d];
            atomicAdd(&out[j], cst*inv);
        }
    }

    float er0 = g_er0, el0 = g_el0;
    int nChunk = (BN + 31) >> 5;
    for (int ch = gwarp; ch < nChunk; ch += nwarp){
        int i2 = ch*32 + lane;
        int head = (i2 < BN) ? g_head[i2] : -1;
        unsigned bal = __ballot_sync(0xffffffffu, head >= 0);
        while (bal){
            int l = __ffs(bal) - 1; bal &= bal - 1;
            int i2t  = __shfl_sync(0xffffffffu, i2, l);
            int cur  = __shfl_sync(0xffffffffu, head, l);
            float dphir = g_dphir[i2t];
            float acc0 = 0.f, acc1 = 0.f, den = 0.f;
            int cnt = 0;
            while (cur >= 0){
                int k = g_ch_k[cur];
                float w = expf(leakyf(g_philc[k] + er0 + dphir));
                den += w; cnt++;
                const float* h2 = &g_H2c[(size_t)k*DD];
                acc0 += w*h2[lane];
                acc1 += w*h2[lane + 32];
                cur = g_ch_nx[cur];
            }
            int b = i2t / NN, v = i2t - b*NN;
            int nb = g_deg[v] - cnt;
            if (nb > 0){
                float bw = (float)nb * expf(leakyf(el0 + er0 + dphir));
                den  += bw;
                acc0 += bw*g_H0[lane];
                acc1 += bw*g_H0[lane + 32];
            }
            float rden = 1.0f / den;
            float v0 = fmaxf(acc0*rden + b2[lane],      0.f) - g_G1[lane];
            float v1 = fmaxf(acc1*rden + b2[lane + 32], 0.f) - g_G1[lane + 32];
            atomicAdd(&out[b*DD + lane],      v0*inv);
            atomicAdd(&out[b*DD + lane + 32], v1*inv);
        }
    }
}

// ---------------- launch ----------------
extern "C" void kernel_launch(void* const* d_in, const int* in_sizes, int n_in,
                              void* d_out, int out_size){
    const int*   hist  = (const int*)  d_in[0];
    const int*   exits = (const int*)  d_in[1];
    const int*   src   = (const int*)  d_in[2];
    const int*   dst   = (const int*)  d_in[3];
    const float* W1    = (const float*)d_in[4];
    const float* al1   = (const float*)d_in[5];
    const float* ar1   = (const float*)d_in[6];
    const float* b1    = (const float*)d_in[7];
    const float* W2    = (const float*)d_in[8];
    const float* al2   = (const float*)d_in[9];
    const float* ar2   = (const float*)d_in[10];
    const float* b2    = (const float*)d_in[11];
    float* out = (float*)d_out;
    int E   = in_sizes[2];
    int nex = in_sizes[1];

    k_init<<<514, 256>>>(hist, exits, nex, W1, al1, ar1, b1, W2, al2, ar2, b2, out);
    int eb = ((E >> 2) + 255) / 256;
    if (eb < 1) eb = 1;
    if (eb > 2048) eb = 2048;
    k_scan1<<<eb, 256>>>(src, dst, E);
    k_node<<<(BN + 255)/256, 256>>>();
    k_de<<<1024, 256>>>(W1, b1, W2, src, dst, E);
    k_final<<<512, 256>>>(out, b2);
}

// round 7
// speedup vs baseline: 2.4089x; 2.1388x over previous
#include <cuda_runtime.h>

#define NN 50000
#define BB 8
#define BN (BB*NN)
#define DD 64
#define HISTLEN 50
#define NW ((NN+31)/32)      /* 1563 bitmap words */
#define L1_CAP (1<<16)
#define L2_CAP (1<<20)
#define CH_CAP (1<<21)

// ---------------- static device scratch ----------------
__device__ float g_cl, g_cr, g_el0, g_er0;
__device__ float g_wal[DD], g_war[DD], g_h0[DD], g_H0[DD], g_G1[DD], g_G0[DD];

__device__ unsigned g_code[NN];
__device__ int      g_deg[NN];
__device__ unsigned g_mask[NN];
__device__ unsigned g_bm1[NW];     // bitmap: feature-special sources
__device__ unsigned g_bm2[NW];     // bitmap: layer-2 special sources
__device__ unsigned g_counts[BN];
__device__ float    g_dphir[BN];
__device__ int      g_idxK[BN];
__device__ int      g_head[BN];
__device__ int      g_l1[L1_CAP];  // compact list of layer-1 special (b,v)
__device__ int      g_l2[L2_CAP];  // compact list of touched layer-2 (b,dst)
__device__ float    g_philc[L1_CAP];
__device__ float    g_H2c[(size_t)L1_CAP*DD];
__device__ int      g_ch_k[CH_CAP];
__device__ int      g_ch_nx[CH_CAP];
__device__ int g_ctrL1, g_ctrC, g_ctrL2, g_deg0;

__device__ __forceinline__ float leakyf(float x){ return x > 0.f ? x : 0.2f*x; }

// ---------------- K_A: init + feature scatter + constants ----------------
__global__ void k_init(const int* __restrict__ hist, const int* __restrict__ exits, int n_exits,
                       const float* __restrict__ W1, const float* __restrict__ al1,
                       const float* __restrict__ ar1, const float* __restrict__ b1,
                       const float* __restrict__ W2, const float* __restrict__ al2,
                       const float* __restrict__ ar2, const float* __restrict__ b2,
                       float* out){
    int tid = threadIdx.x, bid = blockIdx.x;
    if (bid == 0){
        for (int i = tid; i < NN; i += 256) g_code[i] = 0u;
        for (int i = tid; i < NW; i += 256) g_bm1[i] = 0u;
        __syncthreads();
        for (int i = tid; i < BB*n_exits; i += 256){
            int b = i / n_exits; int v = exits[i - b*n_exits];
            atomicOr(&g_code[v], 1u << (4*b));
            atomicOr(&g_bm1[v >> 5], 1u << (v & 31));
        }
        __syncthreads();
        for (int i = tid; i < BB*(HISTLEN-1); i += 256){
            int b = i / (HISTLEN-1); int j = i - b*(HISTLEN-1);
            int v = hist[b*HISTLEN + j]; int sh = 4*b;
            atomicAnd(&g_code[v], ~(0xFu << sh));
            atomicOr (&g_code[v], 2u << sh);
            atomicOr (&g_bm1[v >> 5], 1u << (v & 31));
        }
        __syncthreads();
        if (tid < BB){
            int v = hist[tid*HISTLEN + HISTLEN-1]; int sh = 4*tid;
            atomicAnd(&g_code[v], ~(0xFu << sh));
            atomicOr (&g_code[v], 3u << sh);
            atomicOr (&g_bm1[v >> 5], 1u << (v & 31));
        }
    } else if (bid == 1){
        if (tid < DD){
            float wl = 0.f, wr = 0.f;
            for (int j = 0; j < DD; j++){ float w = W2[tid*DD + j]; wl += w*al2[j]; wr += w*ar2[j]; }
            g_wal[tid] = wl; g_war[tid] = wr;
            g_h0[tid] = fmaxf(b1[tid], 0.f);
        }
        __syncthreads();
        if (tid < DD){
            float h = 0.f;
            for (int j = 0; j < DD; j++) h += g_h0[j]*W2[j*DD + tid];
            g_H0[tid] = h;
            g_G1[tid] = fmaxf(h + b2[tid], 0.f);
            g_G0[tid] = fmaxf(b2[tid], 0.f);
        }
        if (tid == 0){
            float cl = 0.f, cr = 0.f;
            for (int j = 0; j < DD; j++){ cl += W1[j]*al1[j]; cr += W1[j]*ar1[j]; }
            g_cl = cl; g_cr = cr;
        }
        __syncthreads();
        if (tid == 0){
            float el = 0.f, er = 0.f;
            for (int j = 0; j < DD; j++){ el += g_h0[j]*g_wal[j]; er += g_h0[j]*g_war[j]; }
            g_el0 = el; g_er0 = er;
        }
        if (tid == 32){ g_ctrL1 = 0; g_ctrC = 0; g_ctrL2 = 0; g_deg0 = 0; }
    } else {
        int g = (bid - 2)*256 + tid;
        int gs = (gridDim.x - 2)*256;
        for (int i = g; i < BN; i += gs){
            g_counts[i] = 0u; g_dphir[i] = 0.f; g_head[i] = -1;
        }
        for (int i = g; i < NN; i += gs){ g_deg[i] = 0; g_mask[i] = 0u; }
        for (int i = g; i < NW; i += gs) g_bm2[i] = 0u;
        if (g < BB*DD) out[g] = 0.f;
    }
}

// ---------------- K_B: edge scan 1 (bitmap-filtered) ----------------
__device__ __forceinline__ void scan1_slow(int sv, int dv){
    unsigned c = g_code[sv];
    while (c){
        int bit = __ffs(c) - 1;
        int b   = bit >> 2;
        unsigned cls = (c >> (4*b)) & 0xFu;
        c &= ~(0xFu << (4*b));
        int i2 = b*NN + dv;
        unsigned old = atomicAdd(&g_counts[i2], 1u << (10*(cls-1)));
        if (old == 0u){
            int p = atomicAdd(&g_ctrL1, 1);
            if (p < L1_CAP) g_l1[p] = i2;
        }
    }
}

__global__ void k_scan1(const int* __restrict__ src, const int* __restrict__ dst, int E){
    __shared__ unsigned sbm[NW];
    int tid = threadIdx.x;
    for (int i = tid; i < NW; i += 256) sbm[i] = g_bm1[i];
    __syncthreads();
    int g = blockIdx.x*256 + tid;
    int gs = gridDim.x*256;
    int E4 = E >> 2;
    const int4* s4 = (const int4*)src;
    const int4* d4 = (const int4*)dst;
    for (int i = g; i < E4; i += gs){
        int4 sv = __ldg(&s4[i]); int4 dv = __ldg(&d4[i]);
        atomicAdd(&g_deg[dv.x], 1); atomicAdd(&g_deg[dv.y], 1);
        atomicAdd(&g_deg[dv.z], 1); atomicAdd(&g_deg[dv.w], 1);
        if ((sbm[sv.x >> 5] >> (sv.x & 31)) & 1u) scan1_slow(sv.x, dv.x);
        if ((sbm[sv.y >> 5] >> (sv.y & 31)) & 1u) scan1_slow(sv.y, dv.y);
        if ((sbm[sv.z >> 5] >> (sv.z & 31)) & 1u) scan1_slow(sv.z, dv.z);
        if ((sbm[sv.w >> 5] >> (sv.w & 31)) & 1u) scan1_slow(sv.w, dv.w);
    }
    for (int i = (E4 << 2) + g; i < E; i += gs){
        int sv = src[i], dv = dst[i];
        atomicAdd(&g_deg[dv], 1);
        if ((sbm[sv >> 5] >> (sv & 31)) & 1u) scan1_slow(sv, dv);
    }
}

// ---------------- K_C: per special slot (warp/entry) + deg0 ----------------
__global__ void k_prep2(const float* __restrict__ W1, const float* __restrict__ b1,
                        const float* __restrict__ W2){
    __shared__ float sW2[DD*DD];
    __shared__ float sh1[8][DD];
    __shared__ float scst[4*DD];   // W1 | b1 | wal | war
    int tid = threadIdx.x;
    // deg0 count (independent of smem)
    {
        int g = blockIdx.x*256 + tid;
        int gs = gridDim.x*256;
        int cnt = 0;
        for (int v = g; v < NN; v += gs) if (g_deg[v] == 0) cnt++;
        #pragma unroll
        for (int o = 16; o; o >>= 1) cnt += __shfl_xor_sync(0xffffffffu, cnt, o);
        if ((tid & 31) == 0 && cnt) atomicAdd(&g_deg0, cnt);
    }
    for (int j = tid; j < DD*DD; j += 256) sW2[j] = W2[j];
    if (tid < DD){
        scst[tid]        = W1[tid];
        scst[DD + tid]   = b1[tid];
        scst[2*DD + tid] = g_wal[tid];
        scst[3*DD + tid] = g_war[tid];
    }
    __syncthreads();

    int K = g_ctrL1; if (K > L1_CAP) K = L1_CAP;
    int wid = tid >> 5, lane = tid & 31;
    int gwarp = blockIdx.x*8 + wid, nwarp = gridDim.x*8;
    float er0 = g_er0, cl = g_cl, cr = g_cr;
    for (int e = gwarp; e < K; e += nwarp){
        int i = g_l1[e];
        int b = i / NN, v = i - b*NN;
        float s;
        if (lane == 0){
            unsigned c = g_counts[i];
            int degv = g_deg[v];
            int n1 = c & 1023, n2 = (c >> 10) & 1023, n3 = (c >> 20) & 1023;
            int n0 = degv - n1 - n2 - n3;
            unsigned clsv = (g_code[v] >> (4*b)) & 0xFu;
            float fd = (clsv == 0) ? 0.f : (clsv == 1 ? 1.0f : (clsv == 2 ? 0.1f : 0.5f));
            float crfd = cr*fd;
            float w0 = (n0 > 0) ? n0*expf(leakyf(crfd))           : 0.f;
            float w1 = (n1 > 0) ? n1*expf(leakyf(cl*1.0f + crfd)) : 0.f;
            float w2 = (n2 > 0) ? n2*expf(leakyf(cl*0.1f + crfd)) : 0.f;
            float w3 = (n3 > 0) ? n3*expf(leakyf(cl*0.5f + crfd)) : 0.f;
            s = (1.0f*w1 + 0.1f*w2 + 0.5f*w3) / (w0 + w1 + w2 + w3);
        }
        s = __shfl_sync(0xffffffffu, s, 0);
        float h0 = fmaxf(s*scst[lane]      + scst[DD + lane],      0.f);
        float h1 = fmaxf(s*scst[lane + 32] + scst[DD + lane + 32], 0.f);
        sh1[wid][lane] = h0; sh1[wid][lane + 32] = h1;
        float pl = h0*scst[2*DD + lane] + h1*scst[2*DD + lane + 32];
        float pr = h0*scst[3*DD + lane] + h1*scst[3*DD + lane + 32];
        #pragma unroll
        for (int o = 16; o; o >>= 1){
            pl += __shfl_xor_sync(0xffffffffu, pl, o);
            pr += __shfl_xor_sync(0xffffffffu, pr, o);
        }
        __syncwarp();
        if (lane == 0){
            g_philc[e] = pl;
            g_dphir[i] = pr - er0;
            g_idxK[i]  = e;
            atomicOr(&g_mask[v], 1u << b);
            atomicOr(&g_bm2[v >> 5], 1u << (v & 31));
        }
        float a0 = 0.f, a1 = 0.f;
        #pragma unroll 8
        for (int j = 0; j < DD; j++){
            float hv = sh1[wid][j];
            a0 += hv*sW2[j*DD + lane];
            a1 += hv*sW2[j*DD + lane + 32];
        }
        g_H2c[(size_t)e*DD + lane]      = a0;
        g_H2c[(size_t)e*DD + lane + 32] = a1;
        __syncwarp();
    }
}

// ---------------- K_D: edge scan 2 (bitmap-filtered chain push) ----------------
__device__ __forceinline__ void scan2_slow(int sv, int dv){
    unsigned m = g_mask[sv];
    while (m){
        int b = __ffs(m) - 1; m &= m - 1;
        int i2 = b*NN + dv;
        int pos = atomicAdd(&g_ctrC, 1);
        if (pos < CH_CAP){
            g_ch_k[pos] = g_idxK[b*NN + sv];
            int old = atomicExch(&g_head[i2], pos);
            g_ch_nx[pos] = old;
            if (old == -1){
                int p = atomicAdd(&g_ctrL2, 1);
                if (p < L2_CAP) g_l2[p] = i2;
            }
        }
    }
}

__global__ void k_scan2(const int* __restrict__ src, const int* __restrict__ dst, int E){
    __shared__ unsigned sbm[NW];
    int tid = threadIdx.x;
    for (int i = tid; i < NW; i += 256) sbm[i] = g_bm2[i];
    __syncthreads();
    int g = blockIdx.x*256 + tid;
    int gs = gridDim.x*256;
    int E4 = E >> 2;
    const int4* s4 = (const int4*)src;
    for (int i = g; i < E4; i += gs){
        int4 sv = __ldg(&s4[i]);
        if ((sbm[sv.x >> 5] >> (sv.x & 31)) & 1u) scan2_slow(sv.x, __ldg(&dst[4*i]));
        if ((sbm[sv.y >> 5] >> (sv.y & 31)) & 1u) scan2_slow(sv.y, __ldg(&dst[4*i+1]));
        if ((sbm[sv.z >> 5] >> (sv.z & 31)) & 1u) scan2_slow(sv.z, __ldg(&dst[4*i+2]));
        if ((sbm[sv.w >> 5] >> (sv.w & 31)) & 1u) scan2_slow(sv.w, __ldg(&dst[4*i+3]));
    }
    for (int i = (E4 << 2) + g; i < E; i += gs){
        int sv = src[i];
        if ((sbm[sv >> 5] >> (sv & 31)) & 1u) scan2_slow(sv, dst[i]);
    }
}

// ---------------- K_E: chain walk + finalize ----------------
__global__ void k_final(float* out, const float* __restrict__ b2){
    __shared__ float sacc[BB][DD];
    int tid = threadIdx.x;
    int wid = tid >> 5, lane = tid & 31;
    const float inv = 1.0f / (float)NN;
    for (int j = tid; j < BB*DD; j += 256) ((float*)sacc)[j] = 0.f;
    __syncthreads();

    float er0 = g_er0, el0 = g_el0;
    float b2a = b2[lane], b2b = b2[lane + 32];
    float G1a = g_G1[lane], G1b = g_G1[lane + 32];
    float H0a = g_H0[lane], H0b = g_H0[lane + 32];

    int S = g_ctrL2; if (S > L2_CAP) S = L2_CAP;
    int gwarp = blockIdx.x*8 + wid, nwarp = gridDim.x*8;
    for (int e = gwarp; e < S; e += nwarp){
        int i2 = g_l2[e];
        int b = i2 / NN, v = i2 - b*NN;
        float dphir = g_dphir[i2];
        int cur = g_head[i2];
        float acc0 = 0.f, acc1 = 0.f, den = 0.f;
        int cnt = 0;
        while (cur >= 0){
            int k = g_ch_k[cur];
            float w = expf(leakyf(g_philc[k] + er0 + dphir));
            den += w; cnt++;
            const float* h2 = &g_H2c[(size_t)k*DD];
            acc0 += w*h2[lane];
            acc1 += w*h2[lane + 32];
            cur = g_ch_nx[cur];
        }
        int nb = g_deg[v] - cnt;
        if (nb > 0){
            float bw = (float)nb * expf(leakyf(el0 + er0 + dphir));
            den  += bw;
            acc0 += bw*H0a;
            acc1 += bw*H0b;
        }
        float rden = 1.0f / den;
        float v0 = fmaxf(acc0*rden + b2a, 0.f) - G1a;
        float v1 = fmaxf(acc1*rden + b2b, 0.f) - G1b;
        atomicAdd(&sacc[b][lane],      v0);
        atomicAdd(&sacc[b][lane + 32], v1);
    }
    __syncthreads();
    for (int j = tid; j < BB*DD; j += 256){
        float a = ((float*)sacc)[j];
        if (a != 0.f) atomicAdd(&out[j], a*inv);
    }
    if (blockIdx.x == 0){
        int d0 = g_deg0;
        for (int j = tid; j < BB*DD; j += 256){
            int d = j & (DD-1);
            float cst = (float)(NN - d0)*g_G1[d] + (float)d0*g_G0[d];
            atomicAdd(&out[j], cst*inv);
        }
    }
}

// ---------------- launch ----------------
extern "C" void kernel_launch(void* const* d_in, const int* in_sizes, int n_in,
                              void* d_out, int out_size){
    const int*   hist  = (const int*)  d_in[0];
    const int*   exits = (const int*)  d_in[1];
    const int*   src   = (const int*)  d_in[2];
    const int*   dst   = (const int*)  d_in[3];
    const float* W1    = (const float*)d_in[4];
    const float* al1   = (const float*)d_in[5];
    const float* ar1   = (const float*)d_in[6];
    const float* b1    = (const float*)d_in[7];
    const float* W2    = (const float*)d_in[8];
    const float* al2   = (const float*)d_in[9];
    const float* ar2   = (const float*)d_in[10];
    const float* b2    = (const float*)d_in[11];
    float* out = (float*)d_out;
    int E   = in_sizes[2];
    int nex = in_sizes[1];

    k_init<<<512, 256>>>(hist, exits, nex, W1, al1, ar1, b1, W2, al2, ar2, b2, out);
    int eb = ((E >> 2) + 255) / 256;
    if (eb < 1) eb = 1;
    if (eb > 1024) eb = 1024;
    k_scan1<<<eb, 256>>>(src, dst, E);
    k_prep2<<<1024, 256>>>(W1, b1, W2);
    k_scan2<<<eb, 256>>>(src, dst, E);
    k_final<<<2048, 256>>>(out, b2);
}

// round 8
// speedup vs baseline: 3.1088x; 1.2906x over previous
#include <cuda_runtime.h>

#define NN 50000
#define BB 8
#define BN (BB*NN)
#define DD 64
#define HISTLEN 50
#define NW ((NN+31)/32)      /* 1563 bitmap words */
#define L1_CAP (1<<16)
#define L2_CAP (1<<20)
#define CH_CAP (1<<21)

// ---------------- static device scratch ----------------
__device__ float g_cl, g_cr, g_el0, g_er0;
__device__ float g_wal[DD], g_war[DD], g_h0[DD], g_H0[DD], g_G1[DD], g_G0[DD];

__device__ unsigned g_code[NN];
__device__ int      g_deg[NN];
__device__ unsigned g_mask[NN];
__device__ unsigned g_bm1[NW];     // bitmap: feature-special sources
__device__ unsigned g_bm2[NW];     // bitmap: layer-2 special sources
__device__ unsigned g_counts[BN];
__device__ float    g_dphir[BN];
__device__ int      g_idxK[BN];
__device__ int      g_head[BN];
__device__ int      g_l1[L1_CAP];
__device__ int      g_l2[L2_CAP];
__device__ float    g_philc[L1_CAP];
__device__ float    g_H2c[(size_t)L1_CAP*DD];
__device__ int      g_ch_k[CH_CAP];
__device__ int      g_ch_nx[CH_CAP];
__device__ int g_ctrL1, g_ctrC, g_ctrL2, g_deg0;

__device__ __forceinline__ float leakyf(float x){ return x > 0.f ? x : 0.2f*x; }

// warp-aggregated allocation: each lane wants `cnt` slots from `ctr`.
// returns this lane's base offset (ctr_old + exclusive_prefix).
__device__ __forceinline__ int warp_alloc(int* ctr, int cnt){
    int off = cnt;
    #pragma unroll
    for (int d = 1; d < 32; d <<= 1){
        int n = __shfl_up_sync(0xffffffffu, off, d);
        if ((threadIdx.x & 31) >= d) off += n;
    }
    int total = __shfl_sync(0xffffffffu, off, 31);
    int base = 0;
    if ((threadIdx.x & 31) == 31 && total > 0) base = atomicAdd(ctr, total);
    base = __shfl_sync(0xffffffffu, base, 31);
    return base + off - cnt;
}

// ---------------- K_A: init + feature scatter + constants ----------------
__global__ void k_init(const int* __restrict__ hist, const int* __restrict__ exits, int n_exits,
                       const float* __restrict__ W1, const float* __restrict__ al1,
                       const float* __restrict__ ar1, const float* __restrict__ b1,
                       const float* __restrict__ W2, const float* __restrict__ al2,
                       const float* __restrict__ ar2, const float* __restrict__ b2,
                       float* out){
    int tid = threadIdx.x, bid = blockIdx.x;
    if (bid == 0){
        for (int i = tid; i < NN; i += 256) g_code[i] = 0u;
        for (int i = tid; i < NW; i += 256) g_bm1[i] = 0u;
        __syncthreads();
        for (int i = tid; i < BB*n_exits; i += 256){
            int b = i / n_exits; int v = exits[i - b*n_exits];
            atomicOr(&g_code[v], 1u << (4*b));
            atomicOr(&g_bm1[v >> 5], 1u << (v & 31));
        }
        __syncthreads();
        for (int i = tid; i < BB*(HISTLEN-1); i += 256){
            int b = i / (HISTLEN-1); int j = i - b*(HISTLEN-1);
            int v = hist[b*HISTLEN + j]; int sh = 4*b;
            atomicAnd(&g_code[v], ~(0xFu << sh));
            atomicOr (&g_code[v], 2u << sh);
            atomicOr (&g_bm1[v >> 5], 1u << (v & 31));
        }
        __syncthreads();
        if (tid < BB){
            int v = hist[tid*HISTLEN + HISTLEN-1]; int sh = 4*tid;
            atomicAnd(&g_code[v], ~(0xFu << sh));
            atomicOr (&g_code[v], 3u << sh);
            atomicOr (&g_bm1[v >> 5], 1u << (v & 31));
        }
    } else if (bid == 1){
        if (tid < DD){
            float wl = 0.f, wr = 0.f;
            for (int j = 0; j < DD; j++){ float w = W2[tid*DD + j]; wl += w*al2[j]; wr += w*ar2[j]; }
            g_wal[tid] = wl; g_war[tid] = wr;
            g_h0[tid] = fmaxf(b1[tid], 0.f);
        }
        __syncthreads();
        if (tid < DD){
            float h = 0.f;
            for (int j = 0; j < DD; j++) h += g_h0[j]*W2[j*DD + tid];
            g_H0[tid] = h;
            g_G1[tid] = fmaxf(h + b2[tid], 0.f);
            g_G0[tid] = fmaxf(b2[tid], 0.f);
        }
        if (tid == 0){
            float cl = 0.f, cr = 0.f;
            for (int j = 0; j < DD; j++){ cl += W1[j]*al1[j]; cr += W1[j]*ar1[j]; }
            g_cl = cl; g_cr = cr;
        }
        __syncthreads();
        if (tid == 0){
            float el = 0.f, er = 0.f;
            for (int j = 0; j < DD; j++){ el += g_h0[j]*g_wal[j]; er += g_h0[j]*g_war[j]; }
            g_el0 = el; g_er0 = er;
        }
        if (tid == 32){ g_ctrL1 = 0; g_ctrC = 0; g_ctrL2 = 0; g_deg0 = 0; }
    } else {
        int g = (bid - 2)*256 + tid;
        int gs = (gridDim.x - 2)*256;
        for (int i = g; i < BN; i += gs){
            g_counts[i] = 0u; g_dphir[i] = 0.f; g_head[i] = -1;
        }
        for (int i = g; i < NN; i += gs){ g_deg[i] = 0; g_mask[i] = 0u; }
        for (int i = g; i < NW; i += gs) g_bm2[i] = 0u;
        if (g < BB*DD) out[g] = 0.f;
    }
}

// ---------------- K_B: edge scan 1 (bitmap filter + warp-aggregated list push) ----------------
__global__ void k_scan1(const int* __restrict__ src, const int* __restrict__ dst, int E){
    __shared__ unsigned sbm[NW];
    int tid = threadIdx.x;
    for (int i = tid; i < NW; i += 256) sbm[i] = g_bm1[i];
    __syncthreads();
    int g = blockIdx.x*256 + tid;
    int gs = gridDim.x*256;
    int nIter = (E + gs - 1) / gs;
    for (int it = 0; it < nIter; it++){
        int i = g + it*gs;
        bool valid = (i < E);
        int sv = 0, dv = 0;
        if (valid){ sv = __ldg(&src[i]); dv = __ldg(&dst[i]); }
        if (valid) atomicAdd(&g_deg[dv], 1);
        // first-touch collection (<=8 per edge)
        int i2new[BB]; int nNew = 0;
        if (valid && ((sbm[sv >> 5] >> (sv & 31)) & 1u)){
            unsigned c = g_code[sv];
            while (c){
                int bit = __ffs(c) - 1;
                int b   = bit >> 2;
                unsigned cls = (c >> (4*b)) & 0xFu;
                c &= ~(0xFu << (4*b));
                int i2 = b*NN + dv;
                unsigned old = atomicAdd(&g_counts[i2], 1u << (10*(cls-1)));
                if (old == 0u) i2new[nNew++] = i2;
            }
        }
        int base = warp_alloc(&g_ctrL1, nNew);
        for (int j = 0; j < nNew; j++){
            int p = base + j;
            if (p < L1_CAP) g_l1[p] = i2new[j];
        }
    }
}

// ---------------- K_C: per special slot (warp/entry) + deg0 ----------------
__global__ void k_prep2(const float* __restrict__ W1, const float* __restrict__ b1,
                        const float* __restrict__ W2){
    __shared__ float sW2[DD*DD];
    __shared__ float sh1[8][DD];
    __shared__ float scst[4*DD];   // W1 | b1 | wal | war
    int tid = threadIdx.x;
    {
        int g = blockIdx.x*256 + tid;
        int gs = gridDim.x*256;
        int cnt = 0;
        for (int v = g; v < NN; v += gs) if (g_deg[v] == 0) cnt++;
        #pragma unroll
        for (int o = 16; o; o >>= 1) cnt += __shfl_xor_sync(0xffffffffu, cnt, o);
        if ((tid & 31) == 0 && cnt) atomicAdd(&g_deg0, cnt);
    }
    for (int j = tid; j < DD*DD; j += 256) sW2[j] = W2[j];
    if (tid < DD){
        scst[tid]        = W1[tid];
        scst[DD + tid]   = b1[tid];
        scst[2*DD + tid] = g_wal[tid];
        scst[3*DD + tid] = g_war[tid];
    }
    __syncthreads();

    int K = g_ctrL1; if (K > L1_CAP) K = L1_CAP;
    int wid = tid >> 5, lane = tid & 31;
    int gwarp = blockIdx.x*8 + wid, nwarp = gridDim.x*8;
    float er0 = g_er0, cl = g_cl, cr = g_cr;
    for (int e = gwarp; e < K; e += nwarp){
        int i = g_l1[e];
        int b = i / NN, v = i - b*NN;
        float s;
        if (lane == 0){
            unsigned c = g_counts[i];
            int degv = g_deg[v];
            int n1 = c & 1023, n2 = (c >> 10) & 1023, n3 = (c >> 20) & 1023;
            int n0 = degv - n1 - n2 - n3;
            unsigned clsv = (g_code[v] >> (4*b)) & 0xFu;
            float fd = (clsv == 0) ? 0.f : (clsv == 1 ? 1.0f : (clsv == 2 ? 0.1f : 0.5f));
            float crfd = cr*fd;
            float w0 = (n0 > 0) ? n0*expf(leakyf(crfd))           : 0.f;
            float w1 = (n1 > 0) ? n1*expf(leakyf(cl*1.0f + crfd)) : 0.f;
            float w2 = (n2 > 0) ? n2*expf(leakyf(cl*0.1f + crfd)) : 0.f;
            float w3 = (n3 > 0) ? n3*expf(leakyf(cl*0.5f + crfd)) : 0.f;
            s = (1.0f*w1 + 0.1f*w2 + 0.5f*w3) / (w0 + w1 + w2 + w3);
        }
        s = __shfl_sync(0xffffffffu, s, 0);
        float h0 = fmaxf(s*scst[lane]      + scst[DD + lane],      0.f);
        float h1 = fmaxf(s*scst[lane + 32] + scst[DD + lane + 32], 0.f);
        sh1[wid][lane] = h0; sh1[wid][lane + 32] = h1;
        float pl = h0*scst[2*DD + lane] + h1*scst[2*DD + lane + 32];
        float pr = h0*scst[3*DD + lane] + h1*scst[3*DD + lane + 32];
        #pragma unroll
        for (int o = 16; o; o >>= 1){
            pl += __shfl_xor_sync(0xffffffffu, pl, o);
            pr += __shfl_xor_sync(0xffffffffu, pr, o);
        }
        __syncwarp();
        if (lane == 0){
            g_philc[e] = pl;
            g_dphir[i] = pr - er0;
            g_idxK[i]  = e;
            atomicOr(&g_mask[v], 1u << b);
            atomicOr(&g_bm2[v >> 5], 1u << (v & 31));
        }
        float a0 = 0.f, a1 = 0.f;
        #pragma unroll 8
        for (int j = 0; j < DD; j++){
            float hv = sh1[wid][j];
            a0 += hv*sW2[j*DD + lane];
            a1 += hv*sW2[j*DD + lane + 32];
        }
        g_H2c[(size_t)e*DD + lane]      = a0;
        g_H2c[(size_t)e*DD + lane + 32] = a1;
        __syncwarp();
    }
}

// ---------------- K_D: edge scan 2 (bitmap filter + warp-aggregated pushes) ----------------
__global__ void k_scan2(const int* __restrict__ src, const int* __restrict__ dst, int E){
    __shared__ unsigned sbm[NW];
    int tid = threadIdx.x;
    for (int i = tid; i < NW; i += 256) sbm[i] = g_bm2[i];
    __syncthreads();
    int g = blockIdx.x*256 + tid;
    int gs = gridDim.x*256;
    int nIter = (E + gs - 1) / gs;
    for (int it = 0; it < nIter; it++){
        int i = g + it*gs;
        bool valid = (i < E);
        int sv = 0;
        if (valid) sv = __ldg(&src[i]);
        unsigned m = 0;
        if (valid && ((sbm[sv >> 5] >> (sv & 31)) & 1u)) m = g_mask[sv];
        int cnt = __popc(m);
        // warp-aggregated chain-slot allocation
        int base = warp_alloc(&g_ctrC, cnt);
        int i2new[BB]; int nNew = 0;
        if (m){
            int dv = __ldg(&dst[i]);
            int j = 0;
            do {
                int b = __ffs(m) - 1; m &= m - 1;
                int pos = base + j; j++;
                if (pos < CH_CAP){
                    int i2 = b*NN + dv;
                    g_ch_k[pos] = g_idxK[b*NN + sv];
                    int old = atomicExch(&g_head[i2], pos);
                    g_ch_nx[pos] = old;
                    if (old == -1) i2new[nNew++] = i2;
                }
            } while (m);
        }
        // warp-aggregated touched-dst list push
        int base2 = warp_alloc(&g_ctrL2, nNew);
        for (int j = 0; j < nNew; j++){
            int p = base2 + j;
            if (p < L2_CAP) g_l2[p] = i2new[j];
        }
    }
}

// ---------------- K_E: chain walk + finalize ----------------
__global__ void k_final(float* out, const float* __restrict__ b2){
    __shared__ float sacc[BB][DD];
    int tid = threadIdx.x;
    int wid = tid >> 5, lane = tid & 31;
    const float inv = 1.0f / (float)NN;
    for (int j = tid; j < BB*DD; j += 256) ((float*)sacc)[j] = 0.f;
    __syncthreads();

    float er0 = g_er0, el0 = g_el0;
    float b2a = b2[lane], b2b = b2[lane + 32];
    float G1a = g_G1[lane], G1b = g_G1[lane + 32];
    float H0a = g_H0[lane], H0b = g_H0[lane + 32];

    int S = g_ctrL2; if (S > L2_CAP) S = L2_CAP;
    int gwarp = blockIdx.x*8 + wid, nwarp = gridDim.x*8;
    for (int e = gwarp; e < S; e += nwarp){
        int i2 = g_l2[e];
        int b = i2 / NN, v = i2 - b*NN;
        float dphir = g_dphir[i2];
        int cur = g_head[i2];
        float acc0 = 0.f, acc1 = 0.f, den = 0.f;
        int cnt = 0;
        while (cur >= 0){
            int k = g_ch_k[cur];
            float w = expf(leakyf(g_philc[k] + er0 + dphir));
            den += w; cnt++;
            const float* h2 = &g_H2c[(size_t)k*DD];
            acc0 += w*h2[lane];
            acc1 += w*h2[lane + 32];
            cur = g_ch_nx[cur];
        }
        int nb = g_deg[v] - cnt;
        if (nb > 0){
            float bw = (float)nb * expf(leakyf(el0 + er0 + dphir));
            den  += bw;
            acc0 += bw*H0a;
            acc1 += bw*H0b;
        }
        float rden = 1.0f / den;
        float v0 = fmaxf(acc0*rden + b2a, 0.f) - G1a;
        float v1 = fmaxf(acc1*rden + b2b, 0.f) - G1b;
        atomicAdd(&sacc[b][lane],      v0);
        atomicAdd(&sacc[b][lane + 32], v1);
    }
    __syncthreads();
    for (int j = tid; j < BB*DD; j += 256){
        float a = ((float*)sacc)[j];
        if (a != 0.f) atomicAdd(&out[j], a*inv);
    }
    if (blockIdx.x == 0){
        int d0 = g_deg0;
        for (int j = tid; j < BB*DD; j += 256){
            int d = j & (DD-1);
            float cst = (float)(NN - d0)*g_G1[d] + (float)d0*g_G0[d];
            atomicAdd(&out[j], cst*inv);
        }
    }
}

// ---------------- launch ----------------
extern "C" void kernel_launch(void* const* d_in, const int* in_sizes, int n_in,
                              void* d_out, int out_size){
    const int*   hist  = (const int*)  d_in[0];
    const int*   exits = (const int*)  d_in[1];
    const int*   src   = (const int*)  d_in[2];
    const int*   dst   = (const int*)  d_in[3];
    const float* W1    = (const float*)d_in[4];
    const float* al1   = (const float*)d_in[5];
    const float* ar1   = (const float*)d_in[6];
    const float* b1    = (const float*)d_in[7];
    const float* W2    = (const float*)d_in[8];
    const float* al2   = (const float*)d_in[9];
    const float* ar2   = (const float*)d_in[10];
    const float* b2    = (const float*)d_in[11];
    float* out = (float*)d_out;
    int E   = in_sizes[2];
    int nex = in_sizes[1];

    k_init<<<512, 256>>>(hist, exits, nex, W1, al1, ar1, b1, W2, al2, ar2, b2, out);
    int eb = (E + 255) / 256;
    if (eb < 1) eb = 1;
    if (eb > 1024) eb = 1024;
    k_scan1<<<eb, 256>>>(src, dst, E);
    k_prep2<<<1024, 256>>>(W1, b1, W2);
    k_scan2<<<eb, 256>>>(src, dst, E);
    k_final<<<1024, 256>>>(out, b2);
}

// round 9
// speedup vs baseline: 3.5400x; 1.1387x over previous
#include <cuda_runtime.h>

#define NN 50000
#define BB 8
#define BN (BB*NN)
#define DD 64
#define HISTLEN 50
#define NW ((NN+31)/32)      /* 1563 bitmap words */
#define L1_CAP (1<<16)
#define L2_CAP (1<<20)
#define CH_CAP (1<<23)       /* >= 8*E for E<=1M */

// ---------------- static device scratch ----------------
__device__ float g_cl, g_cr, g_el0, g_er0;
__device__ float g_wal[DD], g_war[DD], g_h0[DD], g_H0[DD], g_G1[DD], g_G0[DD];

__device__ unsigned g_code[NN];
__device__ int      g_deg[NN];
__device__ unsigned g_mask[NN];
__device__ unsigned g_bm1[NW];
__device__ unsigned g_bm2[NW];
__device__ unsigned g_counts[BN];
__device__ float    g_dphir[BN];
__device__ int      g_idxK[BN];
__device__ int      g_head[BN];
__device__ int      g_l1[L1_CAP];
__device__ int      g_l2[L2_CAP];
__device__ float    g_philc[L1_CAP];
__device__ float    g_H2c[(size_t)L1_CAP*DD];
__device__ int      g_ch_k[CH_CAP];   // chain node (indexed by edge*8+b): special slot k
__device__ int      g_ch_nx[CH_CAP];  // chain node: next
__device__ int g_ctrL1, g_ctrL2, g_deg0;

__device__ __forceinline__ float leakyf(float x){ return x > 0.f ? x : 0.2f*x; }

// ---------------- K0: wide zero ----------------
__global__ void k_init(float* out){
    int g = blockIdx.x*256 + threadIdx.x;
    int gs = gridDim.x*256;
    for (int i = g; i < BN; i += gs){
        g_counts[i] = 0u; g_dphir[i] = 0.f; g_head[i] = -1;
    }
    for (int i = g; i < NN; i += gs){ g_code[i] = 0u; g_deg[i] = 0; g_mask[i] = 0u; }
    for (int i = g; i < NW; i += gs){ g_bm1[i] = 0u; g_bm2[i] = 0u; }
    if (g < BB*DD) out[g] = 0.f;
    if (g == 0){ g_ctrL1 = 0; g_ctrL2 = 0; g_deg0 = 0; }
}

// ---------------- K1: feature scatter + constants (2 blocks) ----------------
__global__ void k_prep(const int* __restrict__ hist, const int* __restrict__ exits, int n_exits,
                       const float* __restrict__ W1, const float* __restrict__ al1,
                       const float* __restrict__ ar1, const float* __restrict__ b1,
                       const float* __restrict__ W2, const float* __restrict__ al2,
                       const float* __restrict__ ar2, const float* __restrict__ b2){
    int tid = threadIdx.x;
    if (blockIdx.x == 0){
        for (int i = tid; i < BB*n_exits; i += 256){
            int b = i / n_exits; int v = exits[i - b*n_exits];
            atomicOr(&g_code[v], 1u << (4*b));
            atomicOr(&g_bm1[v >> 5], 1u << (v & 31));
        }
        __syncthreads();
        for (int i = tid; i < BB*(HISTLEN-1); i += 256){
            int b = i / (HISTLEN-1); int j = i - b*(HISTLEN-1);
            int v = hist[b*HISTLEN + j]; int sh = 4*b;
            atomicAnd(&g_code[v], ~(0xFu << sh));
            atomicOr (&g_code[v], 2u << sh);
            atomicOr (&g_bm1[v >> 5], 1u << (v & 31));
        }
        __syncthreads();
        if (tid < BB){
            int v = hist[tid*HISTLEN + HISTLEN-1]; int sh = 4*tid;
            atomicAnd(&g_code[v], ~(0xFu << sh));
            atomicOr (&g_code[v], 3u << sh);
            atomicOr (&g_bm1[v >> 5], 1u << (v & 31));
        }
    } else {
        if (tid < DD){
            float wl = 0.f, wr = 0.f;
            for (int j = 0; j < DD; j++){ float w = W2[tid*DD + j]; wl += w*al2[j]; wr += w*ar2[j]; }
            g_wal[tid] = wl; g_war[tid] = wr;
            g_h0[tid] = fmaxf(b1[tid], 0.f);
        }
        __syncthreads();
        if (tid < DD){
            float h = 0.f;
            for (int j = 0; j < DD; j++) h += g_h0[j]*W2[j*DD + tid];
            g_H0[tid] = h;
            g_G1[tid] = fmaxf(h + b2[tid], 0.f);
            g_G0[tid] = fmaxf(b2[tid], 0.f);
        }
        if (tid == 0){
            float cl = 0.f, cr = 0.f;
            for (int j = 0; j < DD; j++){ cl += W1[j]*al1[j]; cr += W1[j]*ar1[j]; }
            g_cl = cl; g_cr = cr;
        }
        __syncthreads();
        if (tid == 0){
            float el = 0.f, er = 0.f;
            for (int j = 0; j < DD; j++){ el += g_h0[j]*g_wal[j]; er += g_h0[j]*g_war[j]; }
            g_el0 = el; g_er0 = er;
        }
    }
}

// block-aggregated list allocation: returns this thread's base slot.
// Uses provided smem. One global atomic per block.
__device__ __forceinline__ int block_alloc(int* ctr, int cnt, int* swt, int* sbase){
    int tid = threadIdx.x, lane = tid & 31, wid = tid >> 5;
    int off = cnt;
    #pragma unroll
    for (int d = 1; d < 32; d <<= 1){
        int n = __shfl_up_sync(0xffffffffu, off, d);
        if (lane >= d) off += n;
    }
    if (lane == 31) swt[wid] = off;
    __syncthreads();
    if (tid == 0){
        int t = 0;
        #pragma unroll
        for (int w = 0; w < 8; w++){ int x = swt[w]; swt[w] = t; t += x; }
        *sbase = (t > 0) ? atomicAdd(ctr, t) : 0;
    }
    __syncthreads();
    return *sbase + swt[wid] + off - cnt;
}

// ---------------- K2: edge scan 1 (one edge/thread) ----------------
__global__ void k_scan1(const int* __restrict__ src, const int* __restrict__ dst, int E){
    __shared__ unsigned sbm[NW];
    __shared__ int swt[8], sbase;
    int tid = threadIdx.x;
    for (int i = tid; i < NW; i += 256) sbm[i] = g_bm1[i];
    __syncthreads();
    int i = blockIdx.x*256 + tid;
    int i2new[BB]; int nNew = 0;
    if (i < E){
        int sv = __ldg(&src[i]);
        int dv = __ldg(&dst[i]);
        atomicAdd(&g_deg[dv], 1);
        if ((sbm[sv >> 5] >> (sv & 31)) & 1u){
            unsigned c = g_code[sv];
            while (c){
                int bit = __ffs(c) - 1;
                int b   = bit >> 2;
                unsigned cls = (c >> (4*b)) & 0xFu;
                c &= ~(0xFu << (4*b));
                int i2 = b*NN + dv;
                unsigned old = atomicAdd(&g_counts[i2], 1u << (10*(cls-1)));
                if (old == 0u) i2new[nNew++] = i2;
            }
        }
    }
    int base = block_alloc(&g_ctrL1, nNew, swt, &sbase);
    for (int j = 0; j < nNew; j++){
        int p = base + j;
        if (p < L1_CAP) g_l1[p] = i2new[j];
    }
}

// ---------------- K3: per special slot (warp/entry) + deg0 ----------------
__global__ void k_prep2(const float* __restrict__ W1, const float* __restrict__ b1,
                        const float* __restrict__ W2){
    __shared__ float sW2[DD*DD];
    __shared__ float sh1[8][DD];
    __shared__ float scst[4*DD];
    int tid = threadIdx.x;
    {
        int g = blockIdx.x*256 + tid;
        int gs = gridDim.x*256;
        int cnt = 0;
        for (int v = g; v < NN; v += gs) if (g_deg[v] == 0) cnt++;
        #pragma unroll
        for (int o = 16; o; o >>= 1) cnt += __shfl_xor_sync(0xffffffffu, cnt, o);
        if ((tid & 31) == 0 && cnt) atomicAdd(&g_deg0, cnt);
    }
    for (int j = tid; j < DD*DD; j += 256) sW2[j] = W2[j];
    if (tid < DD){
        scst[tid]        = W1[tid];
        scst[DD + tid]   = b1[tid];
        scst[2*DD + tid] = g_wal[tid];
        scst[3*DD + tid] = g_war[tid];
    }
    __syncthreads();

    int K = g_ctrL1; if (K > L1_CAP) K = L1_CAP;
    int wid = tid >> 5, lane = tid & 31;
    int gwarp = blockIdx.x*8 + wid, nwarp = gridDim.x*8;
    float er0 = g_er0, cl = g_cl, cr = g_cr;
    for (int e = gwarp; e < K; e += nwarp){
        int i = g_l1[e];
        int b = i / NN, v = i - b*NN;
        float s;
        if (lane == 0){
            unsigned c = g_counts[i];
            int degv = g_deg[v];
            int n1 = c & 1023, n2 = (c >> 10) & 1023, n3 = (c >> 20) & 1023;
            int n0 = degv - n1 - n2 - n3;
            unsigned clsv = (g_code[v] >> (4*b)) & 0xFu;
            float fd = (clsv == 0) ? 0.f : (clsv == 1 ? 1.0f : (clsv == 2 ? 0.1f : 0.5f));
            float crfd = cr*fd;
            float w0 = (n0 > 0) ? n0*expf(leakyf(crfd))           : 0.f;
            float w1 = (n1 > 0) ? n1*expf(leakyf(cl*1.0f + crfd)) : 0.f;
            float w2 = (n2 > 0) ? n2*expf(leakyf(cl*0.1f + crfd)) : 0.f;
            float w3 = (n3 > 0) ? n3*expf(leakyf(cl*0.5f + crfd)) : 0.f;
            s = (1.0f*w1 + 0.1f*w2 + 0.5f*w3) / (w0 + w1 + w2 + w3);
        }
        s = __shfl_sync(0xffffffffu, s, 0);
        float h0 = fmaxf(s*scst[lane]      + scst[DD + lane],      0.f);
        float h1 = fmaxf(s*scst[lane + 32] + scst[DD + lane + 32], 0.f);
        sh1[wid][lane] = h0; sh1[wid][lane + 32] = h1;
        float pl = h0*scst[2*DD + lane] + h1*scst[2*DD + lane + 32];
        float pr = h0*scst[3*DD + lane] + h1*scst[3*DD + lane + 32];
        #pragma unroll
        for (int o = 16; o; o >>= 1){
            pl += __shfl_xor_sync(0xffffffffu, pl, o);
            pr += __shfl_xor_sync(0xffffffffu, pr, o);
        }
        __syncwarp();
        if (lane == 0){
            g_philc[e] = pl;
            g_dphir[i] = pr - er0;
            g_idxK[i]  = e;
            atomicOr(&g_mask[v], 1u << b);
            atomicOr(&g_bm2[v >> 5], 1u << (v & 31));
        }
        float a0 = 0.f, a1 = 0.f;
        #pragma unroll 8
        for (int j = 0; j < DD; j++){
            float hv = sh1[wid][j];
            a0 += hv*sW2[j*DD + lane];
            a1 += hv*sW2[j*DD + lane + 32];
        }
        g_H2c[(size_t)e*DD + lane]      = a0;
        g_H2c[(size_t)e*DD + lane + 32] = a1;
        __syncwarp();
    }
}

// ---------------- K4: edge scan 2 (one edge/thread, atomic-free chain slots) ----------------
__global__ void k_scan2(const int* __restrict__ src, const int* __restrict__ dst, int E){
    __shared__ unsigned sbm[NW];
    __shared__ int swt[8], sbase;
    int tid = threadIdx.x;
    for (int i = tid; i < NW; i += 256) sbm[i] = g_bm2[i];
    __syncthreads();
    int i = blockIdx.x*256 + tid;
    int i2new[BB]; int nNew = 0;
    if (i < E){
        int sv = __ldg(&src[i]);
        if ((sbm[sv >> 5] >> (sv & 31)) & 1u){
            unsigned m = g_mask[sv];
            if (m){
                int dv = __ldg(&dst[i]);
                do {
                    int b = __ffs(m) - 1; m &= m - 1;
                    int i2  = b*NN + dv;
                    int pos = (i << 3) | b;           // unique, no counter
                    if (pos < CH_CAP){
                        g_ch_k[pos] = g_idxK[b*NN + sv];
                        int old = atomicExch(&g_head[i2], pos);
                        g_ch_nx[pos] = old;
                        if (old == -1) i2new[nNew++] = i2;
                    }
                } while (m);
            }
        }
    }
    int base = block_alloc(&g_ctrL2, nNew, swt, &sbase);
    for (int j = 0; j < nNew; j++){
        int p = base + j;
        if (p < L2_CAP) g_l2[p] = i2new[j];
    }
}

// ---------------- K5: chain walk + finalize ----------------
__global__ void k_final(float* out, const float* __restrict__ b2){
    __shared__ float sacc[BB][DD];
    int tid = threadIdx.x;
    int wid = tid >> 5, lane = tid & 31;
    const float inv = 1.0f / (float)NN;
    for (int j = tid; j < BB*DD; j += 256) ((float*)sacc)[j] = 0.f;
    __syncthreads();

    float er0 = g_er0, el0 = g_el0;
    float b2a = b2[lane], b2b = b2[lane + 32];
    float G1a = g_G1[lane], G1b = g_G1[lane + 32];
    float H0a = g_H0[lane], H0b = g_H0[lane + 32];

    int S = g_ctrL2; if (S > L2_CAP) S = L2_CAP;
    int gwarp = blockIdx.x*8 + wid, nwarp = gridDim.x*8;
    for (int e = gwarp; e < S; e += nwarp){
        int i2 = g_l2[e];
        int b = i2 / NN, v = i2 - b*NN;
        float dphir = g_dphir[i2];
        int cur = g_head[i2];
        float acc0 = 0.f, acc1 = 0.f, den = 0.f;
        int cnt = 0;
        while (cur >= 0){
            int k = g_ch_k[cur];
            float w = expf(leakyf(g_philc[k] + er0 + dphir));
            den += w; cnt++;
            const float* h2 = &g_H2c[(size_t)k*DD];
            acc0 += w*h2[lane];
            acc1 += w*h2[lane + 32];
            cur = g_ch_nx[cur];
        }
        int nb = g_deg[v] - cnt;
        if (nb > 0){
            float bw = (float)nb * expf(leakyf(el0 + er0 + dphir));
            den  += bw;
            acc0 += bw*H0a;
            acc1 += bw*H0b;
        }
        float rden = 1.0f / den;
        float v0 = fmaxf(acc0*rden + b2a, 0.f) - G1a;
        float v1 = fmaxf(acc1*rden + b2b, 0.f) - G1b;
        atomicAdd(&sacc[b][lane],      v0);
        atomicAdd(&sacc[b][lane + 32], v1);
    }
    __syncthreads();
    for (int j = tid; j < BB*DD; j += 256){
        float a = ((float*)sacc)[j];
        if (a != 0.f) atomicAdd(&out[j], a*inv);
    }
    if (blockIdx.x == 0){
        int d0 = g_deg0;
        for (int j = tid; j < BB*DD; j += 256){
            int d = j & (DD-1);
            float cst = (float)(NN - d0)*g_G1[d] + (float)d0*g_G0[d];
            atomicAdd(&out[j], cst*inv);
        }
    }
}

// ---------------- launch ----------------
extern "C" void kernel_launch(void* const* d_in, const int* in_sizes, int n_in,
                              void* d_out, int out_size){
    const int*   hist  = (const int*)  d_in[0];
    const int*   exits = (const int*)  d_in[1];
    const int*   src   = (const int*)  d_in[2];
    const int*   dst   = (const int*)  d_in[3];
    const float* W1    = (const float*)d_in[4];
    const float* al1   = (const float*)d_in[5];
    const float* ar1   = (const float*)d_in[6];
    const float* b1    = (const float*)d_in[7];
    const float* W2    = (const float*)d_in[8];
    const float* al2   = (const float*)d_in[9];
    const float* ar2   = (const float*)d_in[10];
    const float* b2    = (const float*)d_in[11];
    float* out = (float*)d_out;
    int E   = in_sizes[2];
    int nex = in_sizes[1];

    int eb = (E + 255) / 256;
    if (eb < 1) eb = 1;

    k_init<<<512, 256>>>(out);
    k_prep<<<2, 256>>>(hist, exits, nex, W1, al1, ar1, b1, W2, al2, ar2, b2);
    k_scan1<<<eb, 256>>>(src, dst, E);
    k_prep2<<<512, 256>>>(W1, b1, W2);
    k_scan2<<<eb, 256>>>(src, dst, E);
    k_final<<<1024, 256>>>(out, b2);
}